// round 5
// baseline (speedup 1.0000x reference)
#include <cuda_runtime.h>
#include <cuda_fp16.h>
#include <mma.h>
#include <cstdint>

using namespace nvcuda;

#define NN 8192
#define CC 256

// ---------------------------------------------------------------------------
// Scratch (__device__ globals; allocation-free rule)
// ---------------------------------------------------------------------------
__device__ float  g_s[NN];                       // d^{-1/2}
__device__ __half g_adjh[(size_t)NN * NN];       // fp16(adj)
__device__ __half g_xsh[NN * CC];                // fp16(s_j * x[j][n])  [K][N]
__device__ __half g_a2h[NN * CC];                // fp16(s_i*(t + s_i*x)) [M][K]
__device__ __half g_wh[CC * CC];                 // fp16(w)  [K][N]

// ---------------------------------------------------------------------------
__device__ __forceinline__ uint32_t smem_u32(const void* p) {
    uint32_t a;
    asm("{ .reg .u64 t; cvta.to.shared.u64 t, %1; cvt.u32.u64 %0, t; }" : "=r"(a) : "l"(p));
    return a;
}
__device__ __forceinline__ void cpa16(uint32_t s, const void* g) {
    asm volatile("cp.async.cg.shared.global [%0], [%1], 16;" :: "r"(s), "l"(g));
}
#define CP_COMMIT() asm volatile("cp.async.commit_group;" ::: "memory")
#define CP_WAIT_2() asm volatile("cp.async.wait_group 2;" ::: "memory")

// ---------------------------------------------------------------------------
// Kernel 1: fused rowsum + f32->fp16 convert of adj.
// ---------------------------------------------------------------------------
__global__ void rowsum_convert_kernel(const float* __restrict__ adj) {
    const int row = blockIdx.x * blockDim.y + threadIdx.y;
    const float4* p = reinterpret_cast<const float4*>(adj + (size_t)row * NN);
    uint2* hout = reinterpret_cast<uint2*>(g_adjh + (size_t)row * NN);
    float sum = 0.0f;
#pragma unroll 4
    for (int i = threadIdx.x; i < NN / 4; i += 32) {
        float4 v = p[i];
        sum += (v.x + v.y) + (v.z + v.w);
        __half2 h0 = __floats2half2_rn(v.x, v.y);
        __half2 h1 = __floats2half2_rn(v.z, v.w);
        uint2 u;
        u.x = *reinterpret_cast<uint32_t*>(&h0);
        u.y = *reinterpret_cast<uint32_t*>(&h1);
        hout[i] = u;
    }
#pragma unroll
    for (int o = 16; o > 0; o >>= 1) sum += __shfl_xor_sync(0xffffffffu, sum, o);
    if (threadIdx.x == 0) g_s[row] = rsqrtf(sum + 1.0f);
}

// ---------------------------------------------------------------------------
__global__ void prep_xs_kernel(const float* __restrict__ x) {
    const int idx = blockIdx.x * 256 + threadIdx.x;   // over NN*CC/4 float4s
    const int row = idx >> 6;                          // CC/4 = 64 per row
    const float s = g_s[row];
    float4 v = reinterpret_cast<const float4*>(x)[idx];
    __half2 h0 = __floats2half2_rn(s * v.x, s * v.y);
    __half2 h1 = __floats2half2_rn(s * v.z, s * v.w);
    uint2 u;
    u.x = *reinterpret_cast<uint32_t*>(&h0);
    u.y = *reinterpret_cast<uint32_t*>(&h1);
    reinterpret_cast<uint2*>(g_xsh)[idx] = u;
}

__global__ void prep_w_kernel(const float* __restrict__ w) {
    const int idx = blockIdx.x * 256 + threadIdx.x;   // over CC*CC/4 float4s
    float4 v = reinterpret_cast<const float4*>(w)[idx];
    __half2 h0 = __floats2half2_rn(v.x, v.y);
    __half2 h1 = __floats2half2_rn(v.z, v.w);
    uint2 u;
    u.x = *reinterpret_cast<uint32_t*>(&h0);
    u.y = *reinterpret_cast<uint32_t*>(&h1);
    reinterpret_cast<uint2*>(g_wh)[idx] = u;
}

// ---------------------------------------------------------------------------
// fp16 WMMA GEMM, tile 64x128, 4-stage cp.async, 2 CTAs/SM.
//   MODE 0: epilogue writes g_a2h = fp16( s_i * (D + s_i * x) )
//   MODE 1: epilogue writes out  = ELU(D)  (f32)
// 256 threads = 8 warps as 2(M) x 4(N); warp tile 32x32.
// ---------------------------------------------------------------------------
constexpr int BM = 64, BN = 128, BK = 64, STAGES = 4;
constexpr int APAD = 72;                   // A smem row stride (halves)
constexpr int BPAD = 136;                  // B smem row stride (halves)
constexpr int A_HALVES = BM * APAD;        // 4608
constexpr int B_HALVES = BK * BPAD;        // 8704
constexpr int STAGE_BYTES = (A_HALVES + B_HALVES) * 2;   // 26624
constexpr int SMEM_BYTES = STAGES * STAGE_BYTES;          // 106496

template <int MODE>
__global__ __launch_bounds__(256, 2)
void gemm_fp16(const __half* __restrict__ A, const __half* __restrict__ B,
               int kA, int k_iters,
               const float* __restrict__ xin, float* __restrict__ outp) {
    extern __shared__ char smem[];
    const uint32_t sb = smem_u32(smem);
    const int tid = threadIdx.x;
    const int warp = tid >> 5;
    const int wm = warp & 1;     // 0..1 along M (32 rows each)
    const int wn = warp >> 1;    // 0..3 along N (32 cols each)
    const int m0 = blockIdx.y * BM;
    const int n0 = blockIdx.x * BN;

    // per-thread load coords: A 64r x 8 chunks (512 -> 2/thr), B 64r x 16 (1024 -> 4/thr)
    const int arr = tid >> 3, arc = (tid & 7) * 8;
    const int brr = tid >> 4, brc = (tid & 15) * 8;
    const __half* gA = A + (size_t)(m0 + arr) * kA + arc;   // +32 rows per rep
    const __half* gB = B + (size_t)brr * CC + n0 + brc;     // +16 rows per rep
    const uint32_t sAo = (arr * APAD + arc) * 2;
    const uint32_t sBo = A_HALVES * 2 + (brr * BPAD + brc) * 2;

    wmma::fragment<wmma::accumulator, 16, 16, 16, float> acc[2][2];
#pragma unroll
    for (int i = 0; i < 2; i++)
#pragma unroll
        for (int j = 0; j < 2; j++) wmma::fill_fragment(acc[i][j], 0.0f);

    auto load_stage = [&](int kt, int s) {
        const uint32_t st = sb + s * STAGE_BYTES;
        const __half* a = gA + kt * BK;
        const __half* b = gB + (size_t)kt * BK * CC;
#pragma unroll
        for (int r = 0; r < 2; r++)
            cpa16(st + sAo + r * (32 * APAD * 2), a + (size_t)(r * 32) * kA);
#pragma unroll
        for (int r = 0; r < 4; r++)
            cpa16(st + sBo + r * (16 * BPAD * 2), b + (size_t)(r * 16) * CC);
    };

    // prologue: stages 0..2
#pragma unroll
    for (int s = 0; s < STAGES - 1; s++) {
        if (s < k_iters) load_stage(s, s);
        CP_COMMIT();
    }

    for (int kt = 0; kt < k_iters; kt++) {
        CP_WAIT_2();
        __syncthreads();   // protects slot (kt-1)&3 rewrite below

        const int nk = kt + STAGES - 1;
        if (nk < k_iters) load_stage(nk, nk & 3);
        CP_COMMIT();

        const __half* Ap = reinterpret_cast<const __half*>(smem + (kt & 3) * STAGE_BYTES);
        const __half* Bp = Ap + A_HALVES;

        // register double-buffered fragments over 4 k-steps
        wmma::fragment<wmma::matrix_a, 16, 16, 16, __half, wmma::row_major> af[2][2];
        wmma::fragment<wmma::matrix_b, 16, 16, 16, __half, wmma::row_major> bf[2][2];
#pragma unroll
        for (int i = 0; i < 2; i++)
            wmma::load_matrix_sync(af[0][i], Ap + (wm * 32 + i * 16) * APAD, APAD);
#pragma unroll
        for (int j = 0; j < 2; j++)
            wmma::load_matrix_sync(bf[0][j], Bp + wn * 32 + j * 16, BPAD);

#pragma unroll
        for (int ks = 0; ks < 4; ks++) {
            const int cu = ks & 1, nx = cu ^ 1;
            if (ks < 3) {
#pragma unroll
                for (int i = 0; i < 2; i++)
                    wmma::load_matrix_sync(af[nx][i],
                        Ap + (wm * 32 + i * 16) * APAD + (ks + 1) * 16, APAD);
#pragma unroll
                for (int j = 0; j < 2; j++)
                    wmma::load_matrix_sync(bf[nx][j],
                        Bp + ((ks + 1) * 16) * BPAD + wn * 32 + j * 16, BPAD);
            }
#pragma unroll
            for (int i = 0; i < 2; i++)
#pragma unroll
                for (int j = 0; j < 2; j++)
                    wmma::mma_sync(acc[i][j], af[cu][i], bf[cu][j], acc[i][j]);
        }
    }
    __syncthreads();   // all MMA smem reads done before staging reuse

    // ---- epilogue: stage accumulators to smem (f32), then fused writeback ----
    float* stg = reinterpret_cast<float*>(smem);   // 64 x 132
#pragma unroll
    for (int i = 0; i < 2; i++)
#pragma unroll
        for (int j = 0; j < 2; j++)
            wmma::store_matrix_sync(stg + (wm * 32 + i * 16) * 132 + wn * 32 + j * 16,
                                    acc[i][j], 132, wmma::mem_row_major);
    __syncthreads();

    const int r = tid >> 2;             // 0..63
    const int c0 = (tid & 3) * 32;      // 0/32/64/96
    const int grow = m0 + r;
    float sA = 0.0f;
    if (MODE == 0) sA = g_s[grow];
#pragma unroll
    for (int c = 0; c < 32; c += 4) {
        float4 v = *reinterpret_cast<const float4*>(stg + r * 132 + c0 + c);
        const int gcol = n0 + c0 + c;
        if (MODE == 0) {
            const float4 xv = *reinterpret_cast<const float4*>(xin + (size_t)grow * CC + gcol);
            __half2 h0 = __floats2half2_rn(sA * (v.x + sA * xv.x), sA * (v.y + sA * xv.y));
            __half2 h1 = __floats2half2_rn(sA * (v.z + sA * xv.z), sA * (v.w + sA * xv.w));
            uint2 u;
            u.x = *reinterpret_cast<uint32_t*>(&h0);
            u.y = *reinterpret_cast<uint32_t*>(&h1);
            *reinterpret_cast<uint2*>(&g_a2h[(size_t)grow * CC + gcol]) = u;
        } else {
            v.x = (v.x > 0.0f) ? v.x : expm1f(v.x);
            v.y = (v.y > 0.0f) ? v.y : expm1f(v.y);
            v.z = (v.z > 0.0f) ? v.z : expm1f(v.z);
            v.w = (v.w > 0.0f) ? v.w : expm1f(v.w);
            *reinterpret_cast<float4*>(&outp[(size_t)grow * CC + gcol]) = v;
        }
    }
}

// ---------------------------------------------------------------------------
extern "C" void kernel_launch(void* const* d_in, const int* in_sizes, int n_in,
                              void* d_out, int out_size) {
    const float *x = nullptr, *adj = nullptr, *w = nullptr;
    for (int i = 0; i < n_in; i++) {
        if (in_sizes[i] == NN * NN) adj = (const float*)d_in[i];
        else if (in_sizes[i] == NN * CC) x = (const float*)d_in[i];
        else if (in_sizes[i] == CC * CC) w = (const float*)d_in[i];
    }
    float* out = (float*)d_out;

    void *p_adjh = nullptr, *p_xsh = nullptr, *p_a2h = nullptr, *p_wh = nullptr;
    cudaGetSymbolAddress(&p_adjh, g_adjh);
    cudaGetSymbolAddress(&p_xsh, g_xsh);
    cudaGetSymbolAddress(&p_a2h, g_a2h);
    cudaGetSymbolAddress(&p_wh, g_wh);

    cudaFuncSetAttribute(gemm_fp16<0>, cudaFuncAttributeMaxDynamicSharedMemorySize, SMEM_BYTES);
    cudaFuncSetAttribute(gemm_fp16<1>, cudaFuncAttributeMaxDynamicSharedMemorySize, SMEM_BYTES);

    rowsum_convert_kernel<<<NN / 8, dim3(32, 8)>>>(adj);
    prep_xs_kernel<<<NN * CC / 4 / 256, 256>>>(x);
    prep_w_kernel<<<CC * CC / 4 / 256, 256>>>(w);
    // grid: blockIdx.x = N tile (2, fast) so the pair sharing an adj row-tile
    // is co-resident -> L2 dedups the A read. 256 CTAs -> all 148 SMs busy,
    // 2 CTAs/SM co-residency for latency hiding.
    gemm_fp16<0><<<dim3(2, 128), 256, SMEM_BYTES>>>(
        (const __half*)p_adjh, (const __half*)p_xsh, NN, NN / BK, x, nullptr);
    gemm_fp16<1><<<dim3(2, 128), 256, SMEM_BYTES>>>(
        (const __half*)p_a2h, (const __half*)p_wh, CC, CC / BK, nullptr, out);
}